// round 2
// baseline (speedup 1.0000x reference)
#include <cuda_runtime.h>
#include <cstdint>

namespace {

constexpr int T_STEPS = 64;
constexpr int NTH     = 256;
constexpr int NBLK    = 4096;
constexpr int ROWS    = 1024;

// bank swizzle: XOR bits[3:4] with bits[6:7]; involutive, preserves 16B quads.
__device__ __forceinline__ int aswz(int i) { return i ^ (((i >> 6) & 3) << 3); }

// cost chain: cn + cb.x*x.x + ... where x is pre-scaled by -2 (|x|^2 term dropped:
// it is constant across states per step, so it cannot change any argmin)
__device__ __forceinline__ float costf(const float4 cb, float cn, const float4 x) {
    return fmaf(cb.w, x.w, fmaf(cb.z, x.z, fmaf(cb.y, x.y, fmaf(cb.x, x.x, cn))));
}

__device__ __forceinline__ float cnrm(const float4 c) {
    return fmaf(c.w, c.w, fmaf(c.z, c.z, fmaf(c.y, c.y, c.x * c.x)));
}

__global__ __launch_bounds__(NTH)
void viterbi_kernel(const float* __restrict__ array,
                    const float* __restrict__ codebook,
                    float* __restrict__ out,
                    int out_size)
{
    __shared__ float alpha[2][1024];              // swizzled layout
    __shared__ float4 xs[T_STEPS];                // -2 * x chunks
    __shared__ unsigned char bp[T_STEPS][256];    // bp[t][aswz(group)]
    __shared__ int   path[T_STEPS];
    __shared__ float redv[8];
    __shared__ int   redi[8];

    const int k  = threadIdx.x;       // 0..255 : state group (owns states 4k..4k+3)
    const int b  = blockIdx.x;
    const int br = b >> 6;
    const int bc = b & 63;
    const int q  = k >> 2;            // quad id
    const int c  = k & 3;             // lane within quad

    // precomputed swizzled indices (all constant per thread)
    const int wz4k = aswz(4 * k);                 // alpha write base (float4)
    const int wzk  = aswz(k);                     // bp index, final sub-step / single step
    const int wzg  = aswz(q + 64 * c);            // bp index, intermediate sub-step
    const int rb   = wzg;                         // alpha read base: aswz(q+64c+256j') = rb+256j'

    // ---- load this block's 256 elements, pre-scaled by -2 ----
    {
        int r = k >> 4, cc = k & 15;
        float v = array[(br * 16 + r) * ROWS + (bc * 16 + cc)];
        reinterpret_cast<float*>(xs)[k] = -2.0f * v;
    }

    // ---- codebook rows in registers ----
    const float4* cb4 = reinterpret_cast<const float4*>(codebook);
    // own output rows 4k..4k+3
    float4 o0 = __ldg(cb4 + 4 * k + 0);
    float4 o1 = __ldg(cb4 + 4 * k + 1);
    float4 o2 = __ldg(cb4 + 4 * k + 2);
    float4 o3 = __ldg(cb4 + 4 * k + 3);
    float on0 = cnrm(o0), on1 = cnrm(o1), on2 = cnrm(o2), on3 = cnrm(o3);
    // intermediate rows k, k+256, k+512, k+768
    float4 i0 = __ldg(cb4 + k + 0);
    float4 i1 = __ldg(cb4 + k + 256);
    float4 i2 = __ldg(cb4 + k + 512);
    float4 i3 = __ldg(cb4 + k + 768);
    float in0 = cnrm(i0), in1 = cnrm(i1), in2 = cnrm(i2), in3 = cnrm(i3);

    __syncthreads();

    // ---- alpha_0 = cost(x0)  (free initial state) -> buffer 1 ----
    float4 x0 = xs[0];
    float v0 = costf(o0, on0, x0);
    float v1 = costf(o1, on1, x0);
    float v2 = costf(o2, on2, x0);
    float v3 = costf(o3, on3, x0);
    *reinterpret_cast<float4*>(&alpha[1][wz4k]) = make_float4(v0, v1, v2, v3);
    __syncthreads();

    // ---- single step t=1: alpha_0 (buf1) -> alpha_1 (buf0) ----
    {
        float a0 = alpha[1][aswz(k)];
        float a1 = alpha[1][aswz(k + 256)];
        float a2 = alpha[1][aswz(k + 512)];
        float a3 = alpha[1][aswz(k + 768)];
        float m = a0; int j = 0;
        if (a1 < m) { m = a1; j = 1; }
        if (a2 < m) { m = a2; j = 2; }
        if (a3 < m) { m = a3; j = 3; }
        bp[1][wzk] = (unsigned char)j;
        float4 xt = xs[1];
        v0 = m + costf(o0, on0, xt);
        v1 = m + costf(o1, on1, xt);
        v2 = m + costf(o2, on2, xt);
        v3 = m + costf(o3, on3, xt);
        *reinterpret_cast<float4*>(&alpha[0][wz4k]) = make_float4(v0, v1, v2, v3);
        __syncthreads();
    }

    const unsigned lb = (unsigned)((k & 31) & ~3);   // quad base lane within warp

    // ---- 31 fused double-steps: alpha_{2p+1} -> alpha_{2p+3} ----
#pragma unroll 2
    for (int p = 0; p < 31; ++p) {
        const float* ap = alpha[p & 1];
        float*       an = alpha[(p & 1) ^ 1];
        const int ti = 2 * p + 2;        // intermediate step index
        const int tf = 2 * p + 3;        // final step index

        // group-min for intermediate group g = q + 64c  (quad-cooperative)
        float a0 = ap[rb];
        float a1 = ap[rb + 256];
        float a2 = ap[rb + 512];
        float a3 = ap[rb + 768];
        float gm = a0; int jj = 0;           // strict <  -> first-occurrence argmin
        if (a1 < gm) { gm = a1; jj = 1; }
        if (a2 < gm) { gm = a2; jj = 2; }
        if (a3 < gm) { gm = a3; jj = 3; }
        bp[ti][wzg] = (unsigned char)jj;

        // quad exchange: gmin for j = 0..3
        float g0 = __shfl_sync(0xffffffffu, gm, lb | 0, 32);
        float g1 = __shfl_sync(0xffffffffu, gm, lb | 1, 32);
        float g2 = __shfl_sync(0xffffffffu, gm, lb | 2, 32);
        float g3 = __shfl_sync(0xffffffffu, gm, lb | 3, 32);

        // intermediate alpha values (registers only), states k + 256j
        float4 xti = xs[ti];
        float c0 = g0 + costf(i0, in0, xti);
        float c1 = g1 + costf(i1, in1, xti);
        float c2 = g2 + costf(i2, in2, xti);
        float c3 = g3 + costf(i3, in3, xti);
        float m = c0; int j = 0;
        if (c1 < m) { m = c1; j = 1; }
        if (c2 < m) { m = c2; j = 2; }
        if (c3 < m) { m = c3; j = 3; }
        bp[tf][wzk] = (unsigned char)j;

        // final sub-step: own states 4k..4k+3
        float4 xtf = xs[tf];
        v0 = m + costf(o0, on0, xtf);
        v1 = m + costf(o1, on1, xtf);
        v2 = m + costf(o2, on2, xtf);
        v3 = m + costf(o3, on3, xtf);
        *reinterpret_cast<float4*>(&an[wz4k]) = make_float4(v0, v1, v2, v3);
        __syncthreads();
    }

    // ---- final argmin over 1024 states (first-occurrence semantics) ----
    float bm = v0; int bi = 4 * k;
    if (v1 < bm) { bm = v1; bi = 4 * k + 1; }
    if (v2 < bm) { bm = v2; bi = 4 * k + 2; }
    if (v3 < bm) { bm = v3; bi = 4 * k + 3; }
#pragma unroll
    for (int off = 16; off; off >>= 1) {
        float om = __shfl_down_sync(0xffffffffu, bm, off);
        int   oi = __shfl_down_sync(0xffffffffu, bi, off);
        if (om < bm || (om == bm && oi < bi)) { bm = om; bi = oi; }
    }
    if ((k & 31) == 0) { redv[k >> 5] = bm; redi[k >> 5] = bi; }
    __syncthreads();

    // ---- backtrack (single thread) ----
    if (k == 0) {
        float m = redv[0]; int s = redi[0];
#pragma unroll
        for (int w = 1; w < 8; ++w) {
            if (redv[w] < m || (redv[w] == m && redi[w] < s)) { m = redv[w]; s = redi[w]; }
        }
        path[T_STEPS - 1] = s;
        for (int t = T_STEPS - 1; t >= 1; --t) {
            int g = s >> 2;
            int j = bp[t][aswz(g)];
            s = g + (j << 8);            // prev = (s>>2) + j*HI, HI = 256
            path[t - 1] = s;
        }
    }
    __syncthreads();

    // ---- emit: rec (exact codebook gather) + states ----
    if (k < T_STEPS) {
        int t = k;
        int s = path[t];
        float4 val = __ldg(cb4 + s);
        int row = br * 16 + (t >> 2);
        int col = bc * 16 + ((t & 3) << 2);
        reinterpret_cast<float4*>(out + row * ROWS + col)[0] = val;
        int sidx = ROWS * ROWS + b * T_STEPS + t;
        if (sidx < out_size) out[sidx] = (float)s;
    }
}

} // namespace

extern "C" void kernel_launch(void* const* d_in, const int* in_sizes, int n_in,
                              void* d_out, int out_size) {
    const float* array    = (const float*)d_in[0];
    const float* codebook = (const float*)d_in[1];
    (void)in_sizes; (void)n_in;
    float* out = (float*)d_out;
    viterbi_kernel<<<NBLK, NTH>>>(array, codebook, out, out_size);
}